// round 3
// baseline (speedup 1.0000x reference)
#include <cuda_runtime.h>
#include <math.h>

#define Bn   32
#define Sn   1024
#define En   128
#define Hn   512
#define Gn   2048
#define Mn   32768
#define NBLK 128

__device__ float g_embed[Mn * En];
__device__ float g_a1[Mn * En];
__device__ float g_a[Mn * 3];
__device__ float g_attn[Mn * 3];
__device__ float g_xproj[(size_t)Mn * Gn];
__device__ float g_enc[(size_t)Mn * Hn];
__device__ float g_ctx[(size_t)Mn * Hn];
__device__ float g_pred[Mn];
__device__ float g_h[2 * Bn * Hn];
__device__ unsigned g_bar_cnt;
__device__ unsigned g_bar_rel;

__device__ __forceinline__ void grid_bar(unsigned phase) {
    __syncthreads();
    if (threadIdx.x == 0) {
        __threadfence();
        unsigned v = atomicAdd(&g_bar_cnt, 1u);
        if (v == phase * (unsigned)NBLK + (unsigned)(NBLK - 1)) {
            __threadfence();
            *(volatile unsigned*)&g_bar_rel = phase + 1u;
        } else {
            while (*(volatile unsigned*)&g_bar_rel < phase + 1u) { __nanosleep(64); }
        }
    }
    __syncthreads();
    __threadfence();
}

__device__ __forceinline__ float sigmoidf_(float x) { return 1.0f / (1.0f + expf(-x)); }

// C[M,N] = act(A[M,K] @ B[N,K]^T + bias1 + bias2); B has row-stride ldb, col offset koff.
__global__ void __launch_bounds__(256) sgemm_kernel(
    const float* __restrict__ A, const float* __restrict__ B, float* __restrict__ C,
    int M, int N, int K, int lda, int ldb, int koff,
    const float* __restrict__ bias1, const float* __restrict__ bias2, int relu)
{
    __shared__ float As[8][128];
    __shared__ float Bs[8][128];
    const int tid = threadIdx.x, bx = blockIdx.x, by = blockIdx.y;
    const int tx = tid & 15, ty = tid >> 4;
    const int arow = tid >> 1, acol = (tid & 1) * 4;
    const float* Ag = A + (size_t)(by * 128 + arow) * lda + acol;
    const float* Bg = B + (size_t)(bx * 128 + arow) * ldb + koff + acol;

    float acc[8][8];
    #pragma unroll
    for (int i = 0; i < 8; ++i)
        #pragma unroll
        for (int j = 0; j < 8; ++j) acc[i][j] = 0.f;

    for (int k0 = 0; k0 < K; k0 += 8) {
        float4 av = *(const float4*)(Ag + k0);
        float b0 = Bg[k0], b1 = Bg[k0 + 1], b2 = Bg[k0 + 2], b3 = Bg[k0 + 3];
        As[acol + 0][arow] = av.x; As[acol + 1][arow] = av.y;
        As[acol + 2][arow] = av.z; As[acol + 3][arow] = av.w;
        Bs[acol + 0][arow] = b0;   Bs[acol + 1][arow] = b1;
        Bs[acol + 2][arow] = b2;   Bs[acol + 3][arow] = b3;
        __syncthreads();
        #pragma unroll
        for (int kk = 0; kk < 8; ++kk) {
            float ra[8], rb[8];
            #pragma unroll
            for (int i = 0; i < 8; ++i) ra[i] = As[kk][ty * 8 + i];
            #pragma unroll
            for (int j = 0; j < 8; ++j) rb[j] = Bs[kk][tx * 8 + j];
            #pragma unroll
            for (int i = 0; i < 8; ++i)
                #pragma unroll
                for (int j = 0; j < 8; ++j) acc[i][j] += ra[i] * rb[j];
        }
        __syncthreads();
    }
    #pragma unroll
    for (int i = 0; i < 8; ++i) {
        int m = by * 128 + ty * 8 + i;
        #pragma unroll
        for (int j = 0; j < 8; ++j) {
            int n = bx * 128 + tx * 8 + j;
            float v = acc[i][j];
            if (bias1) v += bias1[n];
            if (bias2) v += bias2[n];
            if (relu)  v = fmaxf(v, 0.f);
            C[(size_t)m * N + n] = v;
        }
    }
}

__global__ void attn_logits_kernel(const float* __restrict__ a1,
                                   const float* __restrict__ W_a2,
                                   const float* __restrict__ b_a2,
                                   float* __restrict__ a)
{
    int gw = (blockIdx.x * blockDim.x + threadIdx.x) >> 5;
    int lane = threadIdx.x & 31;
    if (gw >= Mn) return;
    float4 v = ((const float4*)(a1 + (size_t)gw * En))[lane];
    #pragma unroll
    for (int l = 0; l < 3; ++l) {
        float4 wv = ((const float4*)(W_a2 + l * En))[lane];
        float s = v.x * wv.x + v.y * wv.y + v.z * wv.z + v.w * wv.w;
        #pragma unroll
        for (int o = 16; o; o >>= 1) s += __shfl_xor_sync(0xffffffffu, s, o);
        if (lane == 0) a[(size_t)gw * 3 + l] = s + b_a2[l];
    }
}

__global__ void softmax_time_kernel(const float* __restrict__ a, float* __restrict__ attn)
{
    __shared__ float red[256];
    int b = blockIdx.x / 3, l = blockIdx.x - b * 3;
    const float* base = a + (size_t)b * Sn * 3 + l;
    float mx = -3.4e38f;
    for (int s = threadIdx.x; s < Sn; s += 256) mx = fmaxf(mx, base[(size_t)s * 3]);
    red[threadIdx.x] = mx; __syncthreads();
    for (int o = 128; o; o >>= 1) {
        if (threadIdx.x < o) red[threadIdx.x] = fmaxf(red[threadIdx.x], red[threadIdx.x + o]);
        __syncthreads();
    }
    mx = red[0]; __syncthreads();
    float sum = 0.f;
    for (int s = threadIdx.x; s < Sn; s += 256) sum += expf(base[(size_t)s * 3] - mx);
    red[threadIdx.x] = sum; __syncthreads();
    for (int o = 128; o; o >>= 1) {
        if (threadIdx.x < o) red[threadIdx.x] += red[threadIdx.x + o];
        __syncthreads();
    }
    float inv = 1.f / red[0];
    float* ob = attn + (size_t)b * Sn * 3 + l;
    for (int s = threadIdx.x; s < Sn; s += 256)
        ob[(size_t)s * 3] = expf(base[(size_t)s * 3] - mx) * inv;
}

__global__ void context_kernel(const float* __restrict__ attn,
                               const float* __restrict__ enc,
                               float* __restrict__ ctx)
{
    int m = blockIdx.x;
    int t = m & (Sn - 1);
    float a0 = attn[(size_t)m * 3 + 0];
    float a1 = attn[(size_t)m * 3 + 1];
    float a2 = attn[(size_t)m * 3 + 2];
    float4 e0 = ((const float4*)(enc + (size_t)m * Hn))[threadIdx.x];
    float4 r; r.x = a0 * e0.x; r.y = a0 * e0.y; r.z = a0 * e0.z; r.w = a0 * e0.w;
    if (t >= 1) {
        float4 e1 = ((const float4*)(enc + (size_t)(m - 1) * Hn))[threadIdx.x];
        r.x += a1 * e1.x; r.y += a1 * e1.y; r.z += a1 * e1.z; r.w += a1 * e1.w;
    }
    if (t >= 2) {
        float4 e2 = ((const float4*)(enc + (size_t)(m - 2) * Hn))[threadIdx.x];
        r.x += a2 * e2.x; r.y += a2 * e2.y; r.z += a2 * e2.z; r.w += a2 * e2.w;
    }
    ((float4*)(ctx + (size_t)m * Hn))[threadIdx.x] = r;
}

__global__ void init_enc_kernel(const float* __restrict__ h0)
{
    int i = blockIdx.x * 256 + threadIdx.x;
    if (i < Bn * Hn) g_h[i] = h0[i & (Hn - 1)];
    if (i == 0) { g_bar_cnt = 0u; *(volatile unsigned*)&g_bar_rel = 0u; }
}

__global__ void init_dec_kernel(const float* __restrict__ h0, const float* __restrict__ b_o2)
{
    int i = blockIdx.x * 256 + threadIdx.x;
    if (i < Bn * Hn) g_h[i] = h0[i & (Hn - 1)];
    if (i < Mn) g_pred[i] = b_o2[0];
    if (i == 0) { g_bar_cnt = 0u; *(volatile unsigned*)&g_bar_rel = 0u; }
}

#define ENC_SMEM ((16 * 512 + 32 * 516 + 128 * 4) * 4)
__global__ void __launch_bounds__(256, 1) lstm_enc_kernel(
    const float* __restrict__ xproj, const float* __restrict__ Whh,
    const float* __restrict__ c0, const int* __restrict__ lengths,
    float* __restrict__ enc_out)
{
    extern __shared__ float sm[];
    float* w_s   = sm;
    float* h_s   = sm + 16 * 512;
    float* red_s = h_s + 32 * 516;

    const int bl = blockIdx.x, tid = threadIdx.x;
    const int half = tid >> 7, tl = tid & 127;
    const int b = tl & 31, jj = tl >> 5;
    const int j = bl * 4 + jj;

    for (int i = tid; i < 16 * 512; i += 256) {
        int lr = i >> 9, k = i & 511;
        int g = lr >> 2, j2 = lr & 3;
        w_s[i] = Whh[(size_t)(g * Hn + bl * 4 + j2) * Hn + k];
    }
    float c_reg = (half == 0) ? c0[j] : 0.f;
    const int len_b = lengths[b];
    __syncthreads();

    const float4* w0 = (const float4*)(w_s + (0 * 4 + jj) * 512);
    const float4* w1 = (const float4*)(w_s + (1 * 4 + jj) * 512);
    const float4* w2 = (const float4*)(w_s + (2 * 4 + jj) * 512);
    const float4* w3 = (const float4*)(w_s + (3 * 4 + jj) * 512);
    const float4* hv = (const float4*)(h_s + b * 516);
    const int kbeg = half * 64, kend = kbeg + 64;

    for (int t = 0; t < Sn; ++t) {
        const float4* src = (const float4*)(g_h + (t & 1) * (Bn * Hn));
        #pragma unroll
        for (int i = 0; i < 16; ++i) {
            int idx = tid + i * 256;
            float4 v = __ldcg(src + idx);
            ((float4*)(h_s + (idx >> 7) * 516))[idx & 127] = v;
        }
        __syncthreads();

        float a0 = 0.f, a1 = 0.f, a2 = 0.f, a3 = 0.f;
        #pragma unroll 8
        for (int kk = kbeg; kk < kend; ++kk) {
            float4 h4 = hv[kk]; float4 v;
            v = w0[kk]; a0 += h4.x * v.x + h4.y * v.y + h4.z * v.z + h4.w * v.w;
            v = w1[kk]; a1 += h4.x * v.x + h4.y * v.y + h4.z * v.z + h4.w * v.w;
            v = w2[kk]; a2 += h4.x * v.x + h4.y * v.y + h4.z * v.z + h4.w * v.w;
            v = w3[kk]; a3 += h4.x * v.x + h4.y * v.y + h4.z * v.z + h4.w * v.w;
        }
        if (half == 1) {
            float* r = red_s + tl * 4;
            r[0] = a0; r[1] = a1; r[2] = a2; r[3] = a3;
        }
        __syncthreads();
        if (half == 0) {
            const float* r  = red_s + tl * 4;
            const float* xp = xproj + (size_t)(b * Sn + t) * Gn + j;
            float gi = a0 + r[0] + xp[0 * Hn];
            float gf = a1 + r[1] + xp[1 * Hn];
            float gg = a2 + r[2] + xp[2 * Hn];
            float go = a3 + r[3] + xp[3 * Hn];
            float si = sigmoidf_(gi), sf = sigmoidf_(gf), so = sigmoidf_(go);
            c_reg = sf * c_reg + si * tanhf(gg);
            float hh = so * tanhf(c_reg);
            __stcg(&g_h[((t + 1) & 1) * (Bn * Hn) + b * Hn + j], hh);
            enc_out[(size_t)(b * Sn + t) * Hn + j] = (t < len_b) ? hh : 0.f;
        }
        grid_bar((unsigned)t);
    }
}

#define DEC_SMEM ((16 * 512 + 32 * 516 + 128 * 4 + 512 + 16) * 4)
__global__ void __launch_bounds__(256, 1) lstm_dec_kernel(
    const float* __restrict__ ctxproj, const float* __restrict__ Whh,
    const float* __restrict__ Wih, const float* __restrict__ c0,
    const float* __restrict__ W_o1, const float* __restrict__ b_o1,
    const float* __restrict__ W_o2)
{
    extern __shared__ float sm[];
    float* w_s   = sm;
    float* h_s   = sm + 16 * 512;
    float* red_s = h_s + 32 * 516;
    float* wo1_s = red_s + 512;
    float* wp_s  = wo1_s + 512;

    const int bl = blockIdx.x, tid = threadIdx.x;
    const int half = tid >> 7, tl = tid & 127;
    const int b = tl & 31, jj = tl >> 5;
    const int j = bl * 4 + jj;

    for (int i = tid; i < 16 * 512; i += 256) {
        int lr = i >> 9, k = i & 511;
        int g = lr >> 2, j2 = lr & 3;
        w_s[i] = Whh[(size_t)(g * Hn + bl * 4 + j2) * Hn + k];
    }
    for (int i = tid; i < 512; i += 256) wo1_s[i] = W_o1[(size_t)bl * Hn + i];
    if (tid < 16) {
        int g = tid >> 2, j2 = tid & 3;
        wp_s[tid] = Wih[(size_t)(g * Hn + bl * 4 + j2) * 513];
    }
    const float wo2 = W_o2[bl];
    const float bo1 = b_o1[bl];
    float c_reg = (half == 0) ? c0[j] : 0.f;
    __syncthreads();

    const float4* w0 = (const float4*)(w_s + (0 * 4 + jj) * 512);
    const float4* w1 = (const float4*)(w_s + (1 * 4 + jj) * 512);
    const float4* w2 = (const float4*)(w_s + (2 * 4 + jj) * 512);
    const float4* w3 = (const float4*)(w_s + (3 * 4 + jj) * 512);
    const float4* hv = (const float4*)(h_s + b * 516);
    const int kbeg = half * 64, kend = kbeg + 64;
    const int warp = tid >> 5, lane = tid & 31;

    for (int t = 0; t < Sn; ++t) {
        const float4* src = (const float4*)(g_h + (t & 1) * (Bn * Hn));
        #pragma unroll
        for (int i = 0; i < 16; ++i) {
            int idx = tid + i * 256;
            float4 v = __ldcg(src + idx);
            ((float4*)(h_s + (idx >> 7) * 516))[idx & 127] = v;
        }
        __syncthreads();

        // output MLP for step t-1 from staged h (h after step t-1)
        if (t > 0) {
            #pragma unroll
            for (int bi = 0; bi < 4; ++bi) {
                int bb = warp * 4 + bi;
                float s = 0.f;
                #pragma unroll
                for (int kk = 0; kk < 16; ++kk) {
                    int k = kk * 32 + lane;
                    s += wo1_s[k] * h_s[bb * 516 + k];
                }
                #pragma unroll
                for (int o = 16; o; o >>= 1) s += __shfl_xor_sync(0xffffffffu, s, o);
                if (lane == 0) {
                    float o1 = fmaxf(s + bo1, 0.f);
                    atomicAdd(&g_pred[bb * Sn + (t - 1)], o1 * wo2);
                }
            }
        }
        grid_bar(2u * (unsigned)t);

        float a0 = 0.f, a1 = 0.f, a2 = 0.f, a3 = 0.f;
        #pragma unroll 8
        for (int kk = kbeg; kk < kend; ++kk) {
            float4 h4 = hv[kk]; float4 v;
            v = w0[kk]; a0 += h4.x * v.x + h4.y * v.y + h4.z * v.z + h4.w * v.w;
            v = w1[kk]; a1 += h4.x * v.x + h4.y * v.y + h4.z * v.z + h4.w * v.w;
            v = w2[kk]; a2 += h4.x * v.x + h4.y * v.y + h4.z * v.z + h4.w * v.w;
            v = w3[kk]; a3 += h4.x * v.x + h4.y * v.y + h4.z * v.z + h4.w * v.w;
        }
        if (half == 1) {
            float* r = red_s + tl * 4;
            r[0] = a0; r[1] = a1; r[2] = a2; r[3] = a3;
        }
        __syncthreads();
        if (half == 0) {
            float p_prev = (t > 0) ? __ldcg(&g_pred[b * Sn + (t - 1)]) : 0.f;
            const float* r  = red_s + tl * 4;
            const float* xp = ctxproj + (size_t)(b * Sn + t) * Gn + j;
            float gi = a0 + r[0] + xp[0 * Hn] + p_prev * wp_s[0 * 4 + jj];
            float gf = a1 + r[1] + xp[1 * Hn] + p_prev * wp_s[1 * 4 + jj];
            float gg = a2 + r[2] + xp[2 * Hn] + p_prev * wp_s[2 * 4 + jj];
            float go = a3 + r[3] + xp[3 * Hn] + p_prev * wp_s[3 * 4 + jj];
            float si = sigmoidf_(gi), sf = sigmoidf_(gf), so = sigmoidf_(go);
            c_reg = sf * c_reg + si * tanhf(gg);
            float hh = so * tanhf(c_reg);
            __stcg(&g_h[((t + 1) & 1) * (Bn * Hn) + b * Hn + j], hh);
        }
        grid_bar(2u * (unsigned)t + 1u);
    }

    // final step's output MLP (t = Sn-1); h after last update sits in g_h[Sn&1]=g_h[0]
    {
        const float4* src = (const float4*)(g_h + (Sn & 1) * (Bn * Hn));
        #pragma unroll
        for (int i = 0; i < 16; ++i) {
            int idx = tid + i * 256;
            float4 v = __ldcg(src + idx);
            ((float4*)(h_s + (idx >> 7) * 516))[idx & 127] = v;
        }
        __syncthreads();
        #pragma unroll
        for (int bi = 0; bi < 4; ++bi) {
            int bb = warp * 4 + bi;
            float s = 0.f;
            #pragma unroll
            for (int kk = 0; kk < 16; ++kk) {
                int k = kk * 32 + lane;
                s += wo1_s[k] * h_s[bb * 516 + k];
            }
            #pragma unroll
            for (int o = 16; o; o >>= 1) s += __shfl_xor_sync(0xffffffffu, s, o);
            if (lane == 0) {
                float o1 = fmaxf(s + bo1, 0.f);
                atomicAdd(&g_pred[bb * Sn + (Sn - 1)], o1 * wo2);
            }
        }
    }
}

__global__ void finalize_kernel(const float* __restrict__ mask, float* __restrict__ out)
{
    int i = blockIdx.x * 256 + threadIdx.x;
    if (i < Mn) out[i] = g_pred[i] * mask[i];
}

extern "C" void kernel_launch(void* const* d_in, const int* in_sizes, int n_in,
                              void* d_out, int out_size)
{
    const float* inputs  = (const float*)d_in[0];
    const float* mask    = (const float*)d_in[1];
    const int*   lengths = (const int*)  d_in[2];
    const float* W_e     = (const float*)d_in[3];
    const float* b_e     = (const float*)d_in[4];
    const float* W_a1    = (const float*)d_in[5];
    const float* b_a1    = (const float*)d_in[6];
    const float* W_a2    = (const float*)d_in[7];
    const float* b_a2    = (const float*)d_in[8];
    const float* Wih_e   = (const float*)d_in[9];
    const float* Whh_e   = (const float*)d_in[10];
    const float* bih_e   = (const float*)d_in[11];
    const float* bhh_e   = (const float*)d_in[12];
    const float* enc_h0  = (const float*)d_in[13];
    const float* enc_c0  = (const float*)d_in[14];
    const float* Wih_d   = (const float*)d_in[15];
    const float* Whh_d   = (const float*)d_in[16];
    const float* bih_d   = (const float*)d_in[17];
    const float* bhh_d   = (const float*)d_in[18];
    const float* dec_h0  = (const float*)d_in[19];
    const float* dec_c0  = (const float*)d_in[20];
    const float* W_o1    = (const float*)d_in[21];
    const float* b_o1    = (const float*)d_in[22];
    const float* W_o2    = (const float*)d_in[23];
    const float* b_o2    = (const float*)d_in[24];
    float* out = (float*)d_out;

    float *p_embed, *p_a1, *p_a, *p_attn, *p_xproj, *p_enc, *p_ctx;
    cudaGetSymbolAddress((void**)&p_embed, g_embed);
    cudaGetSymbolAddress((void**)&p_a1,    g_a1);
    cudaGetSymbolAddress((void**)&p_a,     g_a);
    cudaGetSymbolAddress((void**)&p_attn,  g_attn);
    cudaGetSymbolAddress((void**)&p_xproj, g_xproj);
    cudaGetSymbolAddress((void**)&p_enc,   g_enc);
    cudaGetSymbolAddress((void**)&p_ctx,   g_ctx);

    cudaFuncSetAttribute(lstm_enc_kernel, cudaFuncAttributeMaxDynamicSharedMemorySize, ENC_SMEM);
    cudaFuncSetAttribute(lstm_dec_kernel, cudaFuncAttributeMaxDynamicSharedMemorySize, DEC_SMEM);

    // 1) embed = relu(inputs @ W_e^T + b_e)   (32768 x 128, K=1024)
    sgemm_kernel<<<dim3(En / 128, Mn / 128), 256>>>(
        inputs, W_e, p_embed, Mn, En, 1024, 1024, 1024, 0, b_e, nullptr, 1);
    // 2) a1 = relu(embed @ W_a1^T + b_a1)     (32768 x 128, K=128)
    sgemm_kernel<<<dim3(En / 128, Mn / 128), 256>>>(
        p_embed, W_a1, p_a1, Mn, En, En, En, En, 0, b_a1, nullptr, 1);
    // 3) attention logits + softmax over time
    attn_logits_kernel<<<Mn / 8, 256>>>(p_a1, W_a2, b_a2, p_a);
    softmax_time_kernel<<<Bn * 3, 256>>>(p_a, p_attn);
    // 4) encoder input projection (32768 x 2048, K=128)
    sgemm_kernel<<<dim3(Gn / 128, Mn / 128), 256>>>(
        p_embed, Wih_e, p_xproj, Mn, Gn, En, En, En, 0, bih_e, bhh_e, 0);
    // 5) encoder LSTM (persistent)
    init_enc_kernel<<<(Bn * Hn + 255) / 256, 256>>>(enc_h0);
    lstm_enc_kernel<<<NBLK, 256, ENC_SMEM>>>(p_xproj, Whh_e, enc_c0, lengths, p_enc);
    // 6) context conv
    context_kernel<<<Mn, Hn / 4>>>(p_attn, p_enc, p_ctx);
    // 7) decoder ctx projection (32768 x 2048, K=512), Wih_d cols 1..512
    sgemm_kernel<<<dim3(Gn / 128, Mn / 128), 256>>>(
        p_ctx, Wih_d, p_xproj, Mn, Gn, Hn, Hn, Hn + 1, 1, bih_d, bhh_d, 0);
    // 8) decoder LSTM (persistent) + output MLP
    init_dec_kernel<<<(Mn + 255) / 256, 256>>>(dec_h0, b_o2);
    lstm_dec_kernel<<<NBLK, 256, DEC_SMEM>>>(p_xproj, Whh_d, Wih_d, dec_c0, W_o1, b_o1, W_o2);
    // 9) out = pred * mask
    finalize_kernel<<<(Mn + 255) / 256, 256>>>(mask, out);
}